// round 4
// baseline (speedup 1.0000x reference)
#include <cuda_runtime.h>

// GCN: h1 = relu(Agg(x@W1) + b1); h2 = relu(Agg(h1@W2) + b2);
// h3 = relu(h2@Wf1 + bf1); out = h3@Wf2 + bf2
// Agg(t)[i] = t[i]*dinv[i]^2 + sum_{e: dst=i} t[src_e]*dinv[src]*ew*dinv[i]
// dinv[i] = rsqrt(1 + sum_{e: dst=i} ew_e)

#define NMAX 50000

__device__ float g_t[(size_t)NMAX * 128];    // GEMM raw output (pre-aggregation features)
__device__ float g_agg[(size_t)NMAX * 128];  // aggregation / hidden buffer
__device__ float g_h3[(size_t)NMAX * 128];   // fc1 output
__device__ float g_dinv[NMAX];               // deg, then rsqrt(deg)

// ---------------------------------------------------------------- degree/norm
__global__ void deg_init_kernel(float* deg, int n) {
    int i = blockIdx.x * blockDim.x + threadIdx.x;
    if (i < n) deg[i] = 1.0f;  // self-loop weight
}

__global__ void deg_acc_kernel(float* deg, const int* __restrict__ dst,
                               const float* __restrict__ ew, int e) {
    int i = blockIdx.x * blockDim.x + threadIdx.x;
    if (i < e) atomicAdd(&deg[dst[i]], ew[i]);
}

__global__ void dinv_kernel(float* deg, int n) {
    int i = blockIdx.x * blockDim.x + threadIdx.x;
    if (i < n) deg[i] = rsqrtf(deg[i]);
}

// ---------------------------------------------------------------- scatter-add
__device__ __forceinline__ void red_add_f32x4(float4* p, float4 v) {
    asm volatile("red.global.add.v4.f32 [%0], {%1,%2,%3,%4};"
                 :: "l"(p), "f"(v.x), "f"(v.y), "f"(v.z), "f"(v.w)
                 : "memory");
}

// One warp processes 32 edges; per edge all 32 lanes cover the 128-float row
// (one float4 per lane, 512B contiguous gather + contiguous vectorized RED).
__global__ void scatter_kernel(const float4* __restrict__ t, float4* __restrict__ agg,
                               const int* __restrict__ src, const int* __restrict__ dst,
                               const float* __restrict__ ew, const float* __restrict__ dinv,
                               int e) {
    int warp = (blockIdx.x * blockDim.x + threadIdx.x) >> 5;
    int lane = threadIdx.x & 31;
    int base = warp * 32;
    if (base >= e) return;

    int s = 0, d = 0;
    float nrm = 0.0f;
    int my = base + lane;
    if (my < e) {
        s = src[my];
        d = dst[my];
        nrm = __ldg(&dinv[s]) * ew[my] * __ldg(&dinv[d]);
    }
    const int cnt = min(32, e - base);
    for (int i = 0; i < cnt; i++) {
        int   ss = __shfl_sync(0xffffffffu, s, i);
        int   dd = __shfl_sync(0xffffffffu, d, i);
        float w  = __shfl_sync(0xffffffffu, nrm, i);
        float4 v = __ldg(&t[ss * 32 + lane]);
        red_add_f32x4(&agg[dd * 32 + lane],
                      make_float4(v.x * w, v.y * w, v.z * w, v.w * w));
    }
}

// ---------------------------------------------------------------- bias + relu
__global__ void bias_relu_kernel(float4* h, const float4* __restrict__ bias, int total4) {
    int i = blockIdx.x * blockDim.x + threadIdx.x;
    if (i >= total4) return;
    float4 v = h[i];
    float4 b = bias[i & 31];  // 32 float4s per 128-wide row
    v.x = fmaxf(v.x + b.x, 0.0f);
    v.y = fmaxf(v.y + b.y, 0.0f);
    v.z = fmaxf(v.z + b.z, 0.0f);
    v.w = fmaxf(v.w + b.w, 0.0f);
    h[i] = v;
}

// ---------------------------------------------------------------- GEMM (K=128)
// C[n, COLS] = A[n,128] @ W[128, COLS]  (+bias, relu optional)
// SELF: also write Cs[i,:] = C_raw[i,:] * dinv[i]^2 (self-loop init of agg).
// Block tile: 64 nodes x COLS, 256 threads. A tile + full W staged in SMEM.
template <int COLS, bool ADD_BIAS, bool RELU, bool SELF>
__global__ void __launch_bounds__(256)
gemm128(const float* __restrict__ A, const float* __restrict__ Wg,
        const float* __restrict__ bias, const float* __restrict__ dinv,
        float* __restrict__ C, float* __restrict__ Cs, int n) {
    constexpr int Q      = COLS / 4;   // float4 column groups (32 or 16)
    constexpr int GROUPS = 256 / Q;    // node groups per block
    constexpr int NR     = 64 / GROUPS;// nodes per thread

    extern __shared__ float4 sm[];
    float4* As4 = sm;            // [64][32]  (64 nodes x 128 floats)
    float4* Ws4 = sm + 64 * 32;  // [128][Q]

    int tid   = threadIdx.x;
    int node0 = blockIdx.x * 64;

    for (int idx = tid; idx < 64 * 32; idx += 256) {
        int node = node0 + (idx >> 5);
        As4[idx] = (node < n) ? ((const float4*)A)[node * 32 + (idx & 31)]
                              : make_float4(0.f, 0.f, 0.f, 0.f);
    }
    for (int idx = tid; idx < 128 * Q; idx += 256) {
        Ws4[idx] = ((const float4*)Wg)[idx];
    }
    __syncthreads();

    int qx    = tid % Q;
    int group = tid / Q;

    float4 acc[NR];
#pragma unroll
    for (int i = 0; i < NR; i++) acc[i] = make_float4(0.f, 0.f, 0.f, 0.f);

#pragma unroll 8
    for (int k4 = 0; k4 < 32; k4++) {
        float4 w0 = Ws4[(4 * k4 + 0) * Q + qx];
        float4 w1 = Ws4[(4 * k4 + 1) * Q + qx];
        float4 w2 = Ws4[(4 * k4 + 2) * Q + qx];
        float4 w3 = Ws4[(4 * k4 + 3) * Q + qx];
#pragma unroll
        for (int i = 0; i < NR; i++) {
            float4 a = As4[(group * NR + i) * 32 + k4];
            acc[i].x += a.x * w0.x + a.y * w1.x + a.z * w2.x + a.w * w3.x;
            acc[i].y += a.x * w0.y + a.y * w1.y + a.z * w2.y + a.w * w3.y;
            acc[i].z += a.x * w0.z + a.y * w1.z + a.z * w2.z + a.w * w3.z;
            acc[i].w += a.x * w0.w + a.y * w1.w + a.z * w2.w + a.w * w3.w;
        }
    }

    float4 bv = make_float4(0.f, 0.f, 0.f, 0.f);
    if (ADD_BIAS) bv = ((const float4*)bias)[qx];

#pragma unroll
    for (int i = 0; i < NR; i++) {
        int node = node0 + group * NR + i;
        if (node < n) {
            float4 v = acc[i];
            if (ADD_BIAS) { v.x += bv.x; v.y += bv.y; v.z += bv.z; v.w += bv.w; }
            if (RELU) {
                v.x = fmaxf(v.x, 0.f); v.y = fmaxf(v.y, 0.f);
                v.z = fmaxf(v.z, 0.f); v.w = fmaxf(v.w, 0.f);
            }
            ((float4*)C)[node * Q + qx] = v;
            if (SELF) {
                float di = __ldg(&dinv[node]);
                float s2 = di * di;
                ((float4*)Cs)[node * Q + qx] =
                    make_float4(acc[i].x * s2, acc[i].y * s2, acc[i].z * s2, acc[i].w * s2);
            }
        }
    }
}

// ---------------------------------------------------------------- launcher
extern "C" void kernel_launch(void* const* d_in, const int* in_sizes, int n_in,
                              void* d_out, int out_size) {
    const float* x   = (const float*)d_in[0];
    const int*   ei  = (const int*)d_in[1];
    const float* ew  = (const float*)d_in[2];
    const float* W1  = (const float*)d_in[3];
    const float* b1  = (const float*)d_in[4];
    const float* W2  = (const float*)d_in[5];
    const float* b2  = (const float*)d_in[6];
    const float* Wf1 = (const float*)d_in[7];
    const float* bf1 = (const float*)d_in[8];
    const float* Wf2 = (const float*)d_in[9];
    const float* bf2 = (const float*)d_in[10];

    int n = in_sizes[0] / 128;
    int e = in_sizes[2];
    const int* src = ei;
    const int* dst = ei + e;

    float *t, *agg, *h3, *dinv;
    cudaGetSymbolAddress((void**)&t,    g_t);
    cudaGetSymbolAddress((void**)&agg,  g_agg);
    cudaGetSymbolAddress((void**)&h3,   g_h3);
    cudaGetSymbolAddress((void**)&dinv, g_dinv);

    const int SM128 = (64 * 32 + 128 * 32) * 16;  // 96 KB
    const int SM64  = (64 * 32 + 128 * 16) * 16;  // 64 KB
    cudaFuncSetAttribute(gemm128<128, false, false, true>,
                         cudaFuncAttributeMaxDynamicSharedMemorySize, SM128);
    cudaFuncSetAttribute(gemm128<128, true, true, false>,
                         cudaFuncAttributeMaxDynamicSharedMemorySize, SM128);
    cudaFuncSetAttribute(gemm128<64, true, false, false>,
                         cudaFuncAttributeMaxDynamicSharedMemorySize, SM64);

    int nb = (n + 255) / 256;
    int eb = (e + 255) / 256;
    int gb = (n + 63) / 64;
    int sb = (e + 255) / 256;       // 8 warps/block * 32 edges/warp
    int rb = (n * 32 + 255) / 256;  // float4 elements of a [n,128] buffer

    // degree + symmetric norm
    deg_init_kernel<<<nb, 256>>>(dinv, n);
    deg_acc_kernel<<<eb, 256>>>(dinv, dst, ew, e);
    dinv_kernel<<<nb, 256>>>(dinv, n);

    // conv1: t = x@W1; agg = t*dinv^2 (self loop); scatter edges; h1 = relu(agg+b1)
    gemm128<128, false, false, true><<<gb, 256, SM128>>>(x, W1, nullptr, dinv, t, agg, n);
    scatter_kernel<<<sb, 256>>>((const float4*)t, (float4*)agg, src, dst, ew, dinv, e);
    bias_relu_kernel<<<rb, 256>>>((float4*)agg, (const float4*)b1, n * 32);

    // conv2 (in-place epilogue on agg is safe: each block reads/writes only its rows)
    gemm128<128, false, false, true><<<gb, 256, SM128>>>(agg, W2, nullptr, dinv, t, agg, n);
    scatter_kernel<<<sb, 256>>>((const float4*)t, (float4*)agg, src, dst, ew, dinv, e);
    bias_relu_kernel<<<rb, 256>>>((float4*)agg, (const float4*)b2, n * 32);

    // fc1 + fc2
    gemm128<128, true, true, false><<<gb, 256, SM128>>>(agg, Wf1, bf1, nullptr, h3, nullptr, n);
    gemm128<64, true, false, false><<<gb, 256, SM64>>>(h3, Wf2, bf2, nullptr, (float*)d_out, nullptr, n);
}